// round 3
// baseline (speedup 1.0000x reference)
#include <cuda_runtime.h>
#include <cstdint>
#include <cstddef>

// T=512, B=256, NX=256, NU=256, ND=128, NM=128, NDT=128, NH=512, M=T*B=131072
static constexpr size_t X_OFF     = 0;
static constexpr size_t Y_OFF     = 33554432;
static constexpr size_t SXMIN_OFF = 33685504;
static constexpr size_t SXMAX_OFF = 67239936;
static constexpr size_t SUMIN_OFF = 100794368;
static constexpr size_t SUMAX_OFF = 134348800;

__device__ float g_Aeff[256 * 256];            // [j][i] : x_n[i] = sum_j x[j]*g_Aeff[j*256+i]
__device__ float g_h[(size_t)131072 * 512];    // relu(mu @ hf1^T)
__device__ float g_u[(size_t)131072 * 256];    // relu(h @ hf2^T)

// ---------------- f32x2 helpers ----------------
__device__ __forceinline__ unsigned long long pk2(float a, float b) {
    unsigned long long r;
    asm("mov.b64 %0, {%1, %2};" : "=l"(r) : "r"(__float_as_uint(a)), "r"(__float_as_uint(b)));
    return r;
}
__device__ __forceinline__ unsigned long long bcast2(float v) {
    unsigned long long r;
    unsigned u = __float_as_uint(v);
    asm("mov.b64 %0, {%1, %1};" : "=l"(r) : "r"(u));
    return r;
}
__device__ __forceinline__ void fma2(unsigned long long& d, unsigned long long a, unsigned long long b) {
    asm("fma.rn.f32x2 %0, %1, %2, %0;" : "+l"(d) : "l"(a), "l"(b));
}
__device__ __forceinline__ float2 unpk(unsigned long long v) {
    unsigned lo, hi;
    asm("mov.b64 {%0, %1}, %2;" : "=r"(lo), "=r"(hi) : "l"(v));
    return make_float2(__uint_as_float(lo), __uint_as_float(hi));
}

// ---------------- A_eff prep ----------------
__global__ void build_aeff_kernel(const float* __restrict__ Aw, const float* __restrict__ Asc) {
    int r = blockIdx.x, c = threadIdx.x;
    __shared__ float red[256];
    float w = Aw[r * 256 + c];
    red[c] = w;
    __syncthreads();
#pragma unroll
    for (int s = 128; s > 0; s >>= 1) {
        if (c < s) red[c] = fmaxf(red[c], red[c + s]);
        __syncthreads();
    }
    float mx = red[0];
    __syncthreads();
    float e = expf(w - mx);
    red[c] = e;
    __syncthreads();
#pragma unroll
    for (int s = 128; s > 0; s >>= 1) {
        if (c < s) red[c] += red[c + s];
        __syncthreads();
    }
    float p = e / red[0];
    float sg = 1.f / (1.f + expf(-Asc[r * 256 + c]));
    // A_eff[c][r] (post-transpose) stored as g_Aeff[j*256+i], j=c, i=r
    g_Aeff[c * 256 + r] = (1.f - 0.1f * sg) * p;
}

// ---------------- NT SGEMM, C = A * B^T, fused epilogues ----------------
// MODE 0: A=concat(M_flow,DT) K=256, B=hf1(512x256)      -> g_h = relu(C)
// MODE 1: A=g_h K=512, B=hf2(256x512)                    -> g_u = relu(C), Su_min/max
// MODE 2: A=concat(g_u,D) K=384, B=concat(B_W,E_W)(256x384) -> drive into out X region
template <int MODE>
__global__ void __launch_bounds__(256, 2)
gemm_kernel(const float* __restrict__ pA0, const float* __restrict__ pA1,
            const float* __restrict__ pB0, const float* __restrict__ pB1,
            const float* __restrict__ pUmin, const float* __restrict__ pUmax,
            float* __restrict__ out) {
    constexpr int K = (MODE == 0) ? 256 : (MODE == 1) ? 512 : 384;

    __shared__ float As[16][132];
    __shared__ float Bs[16][132];

    int tid = threadIdx.x;
    int tx = tid & 15, ty = tid >> 4;
    int m0 = blockIdx.y * 128, n0 = blockIdx.x * 128;
    int lm = tid >> 2;       // 0..63
    int lk = (tid & 3) * 4;  // 0,4,8,12

    unsigned long long acc[4][8];
#pragma unroll
    for (int i = 0; i < 4; i++)
#pragma unroll
        for (int j = 0; j < 8; j++) acc[i][j] = 0ULL;

    for (int k0 = 0; k0 < K; k0 += 16) {
        int kg = k0 + lk;
#pragma unroll
        for (int h = 0; h < 2; h++) {
            int ml = lm + h * 64;
            size_t m = (size_t)(m0 + ml);
            float4 v;
            if constexpr (MODE == 0) {
                v = (kg < 128) ? *(const float4*)(pA0 + m * 128 + kg)
                               : *(const float4*)(pA1 + m * 128 + (kg - 128));
            } else if constexpr (MODE == 1) {
                v = *(const float4*)(g_h + m * 512 + kg);
            } else {
                v = (kg < 256) ? *(const float4*)(g_u + m * 256 + kg)
                               : *(const float4*)(pA1 + m * 128 + (kg - 256));
            }
            As[lk + 0][ml] = v.x;
            As[lk + 1][ml] = v.y;
            As[lk + 2][ml] = v.z;
            As[lk + 3][ml] = v.w;
        }
#pragma unroll
        for (int h = 0; h < 2; h++) {
            int nl = lm + h * 64;
            size_t n = (size_t)(n0 + nl);
            float4 v;
            if constexpr (MODE == 0) {
                v = *(const float4*)(pB0 + n * 256 + kg);
            } else if constexpr (MODE == 1) {
                v = *(const float4*)(pB0 + n * 512 + kg);
            } else {
                v = (kg < 256) ? *(const float4*)(pB0 + n * 256 + kg)
                               : *(const float4*)(pB1 + n * 128 + (kg - 256));
            }
            Bs[lk + 0][nl] = v.x;
            Bs[lk + 1][nl] = v.y;
            Bs[lk + 2][nl] = v.z;
            Bs[lk + 3][nl] = v.w;
        }
        __syncthreads();
#pragma unroll
        for (int kk = 0; kk < 16; kk++) {
            ulonglong2 a01 = *(const ulonglong2*)&As[kk][ty * 8];
            ulonglong2 a23 = *(const ulonglong2*)&As[kk][ty * 8 + 4];
            float4 b0v = *(const float4*)&Bs[kk][tx * 8];
            float4 b1v = *(const float4*)&Bs[kk][tx * 8 + 4];
            unsigned long long a2[4] = {a01.x, a01.y, a23.x, a23.y};
            float bn[8] = {b0v.x, b0v.y, b0v.z, b0v.w, b1v.x, b1v.y, b1v.z, b1v.w};
#pragma unroll
            for (int n = 0; n < 8; n++) {
                unsigned long long bb = bcast2(bn[n]);
#pragma unroll
                for (int mp = 0; mp < 4; mp++) fma2(acc[mp][n], a2[mp], bb);
            }
        }
        __syncthreads();
    }

#pragma unroll
    for (int r = 0; r < 8; r++) {
        float c[8];
#pragma unroll
        for (int n = 0; n < 8; n++) {
            float2 v = unpk(acc[r >> 1][n]);
            c[n] = (r & 1) ? v.y : v.x;
        }
        size_t m = (size_t)(m0 + ty * 8 + r);
        size_t col = (size_t)(n0 + tx * 8);

        if constexpr (MODE == 0) {
            size_t base = m * 512 + col;
            *(float4*)(g_h + base) = make_float4(fmaxf(c[0], 0.f), fmaxf(c[1], 0.f),
                                                 fmaxf(c[2], 0.f), fmaxf(c[3], 0.f));
            *(float4*)(g_h + base + 4) = make_float4(fmaxf(c[4], 0.f), fmaxf(c[5], 0.f),
                                                     fmaxf(c[6], 0.f), fmaxf(c[7], 0.f));
        } else if constexpr (MODE == 1) {
            size_t base = m * 256 + col;
            float u[8];
#pragma unroll
            for (int n = 0; n < 8; n++) u[n] = fmaxf(c[n], 0.f);
            *(float4*)(g_u + base) = make_float4(u[0], u[1], u[2], u[3]);
            *(float4*)(g_u + base + 4) = make_float4(u[4], u[5], u[6], u[7]);
            float4 mn0 = *(const float4*)(pUmin + base);
            float4 mn1 = *(const float4*)(pUmin + base + 4);
            float4 mx0 = *(const float4*)(pUmax + base);
            float4 mx1 = *(const float4*)(pUmax + base + 4);
            *(float4*)(out + SUMIN_OFF + base) =
                make_float4(fmaxf(mn0.x - u[0], 0.f), fmaxf(mn0.y - u[1], 0.f),
                            fmaxf(mn0.z - u[2], 0.f), fmaxf(mn0.w - u[3], 0.f));
            *(float4*)(out + SUMIN_OFF + base + 4) =
                make_float4(fmaxf(mn1.x - u[4], 0.f), fmaxf(mn1.y - u[5], 0.f),
                            fmaxf(mn1.z - u[6], 0.f), fmaxf(mn1.w - u[7], 0.f));
            *(float4*)(out + SUMAX_OFF + base) =
                make_float4(fmaxf(u[0] - mx0.x, 0.f), fmaxf(u[1] - mx0.y, 0.f),
                            fmaxf(u[2] - mx0.z, 0.f), fmaxf(u[3] - mx0.w, 0.f));
            *(float4*)(out + SUMAX_OFF + base + 4) =
                make_float4(fmaxf(u[4] - mx1.x, 0.f), fmaxf(u[5] - mx1.y, 0.f),
                            fmaxf(u[6] - mx1.z, 0.f), fmaxf(u[7] - mx1.w, 0.f));
        } else {
            size_t base = m * 256 + col;  // drive -> out X region (scan adds recurrence later)
            *(float4*)(out + X_OFF + base) = make_float4(c[0], c[1], c[2], c[3]);
            *(float4*)(out + X_OFF + base + 4) = make_float4(c[4], c[5], c[6], c[7]);
        }
    }
}

// ---------------- Sequential scan: x_t = x_{t-1} @ A_eff + drive_t ----------------
// 64 CTAs x 4 batch rows, 256 threads. Thread split: jj = tid>>7 (j-parity),
// c = tid&127 (owns columns 2c, 2c+1). x state in smem, packed as row-pairs.
__global__ void __launch_bounds__(256, 1)
scan_kernel(const float* __restrict__ x0, const float* __restrict__ XMIN,
            const float* __restrict__ XMAX, float* __restrict__ out) {
    int b0 = blockIdx.x * 4;
    int tid = threadIdx.x;
    int jj = tid >> 7;
    int c = tid & 127;

    __shared__ unsigned long long xs2[256][2];   // [j][rowpair]
    __shared__ float part[2][128][2][4];         // [jj][c][colpair][row]

    {
        int j = tid;
        float a0 = x0[(b0 + 0) * 256 + j];
        float a1 = x0[(b0 + 1) * 256 + j];
        float a2 = x0[(b0 + 2) * 256 + j];
        float a3 = x0[(b0 + 3) * 256 + j];
        xs2[j][0] = pk2(a0, a1);
        xs2[j][1] = pk2(a2, a3);
    }
    __syncthreads();

    const float* Abase = g_Aeff + 2 * c;

    for (int t = 0; t < 512; t++) {
        unsigned long long acc00 = 0, acc01 = 0, acc10 = 0, acc11 = 0;
#pragma unroll 8
        for (int it = 0; it < 128; it++) {
            int j = 2 * it + jj;
            float2 a = *(const float2*)(Abase + (size_t)j * 256);
            unsigned long long x20 = xs2[j][0];
            unsigned long long x21 = xs2[j][1];
            unsigned long long a0p = bcast2(a.x);
            unsigned long long a1p = bcast2(a.y);
            fma2(acc00, a0p, x20);
            fma2(acc01, a0p, x21);
            fma2(acc10, a1p, x20);
            fma2(acc11, a1p, x21);
        }
        {
            float2 v;
            v = unpk(acc00); part[jj][c][0][0] = v.x; part[jj][c][0][1] = v.y;
            v = unpk(acc01); part[jj][c][0][2] = v.x; part[jj][c][0][3] = v.y;
            v = unpk(acc10); part[jj][c][1][0] = v.x; part[jj][c][1][1] = v.y;
            v = unpk(acc11); part[jj][c][1][2] = v.x; part[jj][c][1][3] = v.y;
        }
        __syncthreads();

        // finalize: thread i handles column i for all 4 rows
        int i = tid;
        int cc = i >> 1, side = i & 1;
        float xn[4];
        size_t rowbase = ((size_t)t * 256 + b0) * 256;
#pragma unroll
        for (int r = 0; r < 4; r++) {
            float s = part[0][cc][side][r] + part[1][cc][side][r];
            size_t idx = rowbase + (size_t)r * 256 + i;
            float dr = out[X_OFF + idx];
            float v = s + dr;
            out[X_OFF + idx] = v;
            out[SXMIN_OFF + idx] = fmaxf(XMIN[idx] - v, 0.f);
            out[SXMAX_OFF + idx] = fmaxf(v - XMAX[idx], 0.f);
            if (i == 255) out[Y_OFF + (size_t)t * 256 + b0 + r] = v;
            xn[r] = v;
        }
        xs2[i][0] = pk2(xn[0], xn[1]);
        xs2[i][1] = pk2(xn[2], xn[3]);
        __syncthreads();
    }
}

// ---------------- launch ----------------
extern "C" void kernel_launch(void* const* d_in, const int* in_sizes, int n_in,
                              void* d_out, int out_size) {
    const float* x      = (const float*)d_in[0];
    const float* M_flow = (const float*)d_in[1];
    const float* DT     = (const float*)d_in[2];
    const float* D      = (const float*)d_in[3];
    const float* XMIN   = (const float*)d_in[4];
    const float* XMAX   = (const float*)d_in[5];
    const float* UMIN   = (const float*)d_in[6];
    const float* UMAX   = (const float*)d_in[7];
    const float* A_w    = (const float*)d_in[8];
    const float* A_sc   = (const float*)d_in[9];
    const float* B_W    = (const float*)d_in[10];
    const float* E_W    = (const float*)d_in[11];
    const float* hf1_W  = (const float*)d_in[12];
    const float* hf2_W  = (const float*)d_in[13];
    float* out = (float*)d_out;

    build_aeff_kernel<<<256, 256>>>(A_w, A_sc);
    gemm_kernel<0><<<dim3(4, 1024), 256>>>(M_flow, DT, hf1_W, nullptr, nullptr, nullptr, out);
    gemm_kernel<1><<<dim3(2, 1024), 256>>>(nullptr, nullptr, hf2_W, nullptr, UMIN, UMAX, out);
    gemm_kernel<2><<<dim3(2, 1024), 256>>>(nullptr, D, B_W, E_W, nullptr, nullptr, out);
    scan_kernel<<<64, 256>>>(x, XMIN, XMAX, out);
}

// round 4
// speedup vs baseline: 1.5545x; 1.5545x over previous
#include <cuda_runtime.h>
#include <cstdint>
#include <cstddef>

// T=512, B=256, NX=256, NU=256, ND=128, NM=128, NDT=128, NH=512, M=T*B=131072
static constexpr size_t X_OFF     = 0;
static constexpr size_t Y_OFF     = 33554432;
static constexpr size_t SXMIN_OFF = 33685504;
static constexpr size_t SXMAX_OFF = 67239936;
static constexpr size_t SUMIN_OFF = 100794368;
static constexpr size_t SUMAX_OFF = 134348800;

__device__ float g_Aeff[256 * 256];            // [j][i] : x_n[i] = sum_j x[j]*g_Aeff[j*256+i]
__device__ float g_h[(size_t)131072 * 512];    // relu(mu @ hf1^T)
__device__ float g_u[(size_t)131072 * 256];    // relu(h @ hf2^T)

// ---------------- f32x2 helpers ----------------
__device__ __forceinline__ unsigned long long pk2(float a, float b) {
    unsigned long long r;
    asm("mov.b64 %0, {%1, %2};" : "=l"(r) : "r"(__float_as_uint(a)), "r"(__float_as_uint(b)));
    return r;
}
__device__ __forceinline__ unsigned long long bcast2(float v) {
    unsigned long long r;
    unsigned u = __float_as_uint(v);
    asm("mov.b64 %0, {%1, %1};" : "=l"(r) : "r"(u));
    return r;
}
__device__ __forceinline__ void fma2(unsigned long long& d, unsigned long long a, unsigned long long b) {
    asm("fma.rn.f32x2 %0, %1, %2, %0;" : "+l"(d) : "l"(a), "l"(b));
}
__device__ __forceinline__ void add2(unsigned long long& d, unsigned long long a) {
    asm("add.rn.f32x2 %0, %0, %1;" : "+l"(d) : "l"(a));
}
__device__ __forceinline__ float2 unpk(unsigned long long v) {
    unsigned lo, hi;
    asm("mov.b64 {%0, %1}, %2;" : "=r"(lo), "=r"(hi) : "l"(v));
    return make_float2(__uint_as_float(lo), __uint_as_float(hi));
}
__device__ __forceinline__ unsigned smem_u32(const void* p) {
    unsigned r;
    asm("{ .reg .u64 t; cvta.to.shared.u64 t, %1; cvt.u32.u64 %0, t; }" : "=r"(r) : "l"(p));
    return r;
}
__device__ __forceinline__ unsigned ctarank() {
    unsigned r;
    asm("mov.u32 %0, %%cluster_ctarank;" : "=r"(r));
    return r;
}

// ---------------- A_eff prep ----------------
__global__ void build_aeff_kernel(const float* __restrict__ Aw, const float* __restrict__ Asc) {
    int r = blockIdx.x, c = threadIdx.x;
    __shared__ float red[256];
    float w = Aw[r * 256 + c];
    red[c] = w;
    __syncthreads();
#pragma unroll
    for (int s = 128; s > 0; s >>= 1) {
        if (c < s) red[c] = fmaxf(red[c], red[c + s]);
        __syncthreads();
    }
    float mx = red[0];
    __syncthreads();
    float e = expf(w - mx);
    red[c] = e;
    __syncthreads();
#pragma unroll
    for (int s = 128; s > 0; s >>= 1) {
        if (c < s) red[c] += red[c + s];
        __syncthreads();
    }
    float p = e / red[0];
    float sg = 1.f / (1.f + expf(-Asc[r * 256 + c]));
    g_Aeff[c * 256 + r] = (1.f - 0.1f * sg) * p;
}

// ---------------- NT SGEMM, C = A * B^T, fused epilogues (unchanged from R3) ----------------
template <int MODE>
__global__ void __launch_bounds__(256, 2)
gemm_kernel(const float* __restrict__ pA0, const float* __restrict__ pA1,
            const float* __restrict__ pB0, const float* __restrict__ pB1,
            const float* __restrict__ pUmin, const float* __restrict__ pUmax,
            float* __restrict__ out) {
    constexpr int K = (MODE == 0) ? 256 : (MODE == 1) ? 512 : 384;

    __shared__ float As[16][132];
    __shared__ float Bs[16][132];

    int tid = threadIdx.x;
    int tx = tid & 15, ty = tid >> 4;
    int m0 = blockIdx.y * 128, n0 = blockIdx.x * 128;
    int lm = tid >> 2;
    int lk = (tid & 3) * 4;

    unsigned long long acc[4][8];
#pragma unroll
    for (int i = 0; i < 4; i++)
#pragma unroll
        for (int j = 0; j < 8; j++) acc[i][j] = 0ULL;

    for (int k0 = 0; k0 < K; k0 += 16) {
        int kg = k0 + lk;
#pragma unroll
        for (int h = 0; h < 2; h++) {
            int ml = lm + h * 64;
            size_t m = (size_t)(m0 + ml);
            float4 v;
            if constexpr (MODE == 0) {
                v = (kg < 128) ? *(const float4*)(pA0 + m * 128 + kg)
                               : *(const float4*)(pA1 + m * 128 + (kg - 128));
            } else if constexpr (MODE == 1) {
                v = *(const float4*)(g_h + m * 512 + kg);
            } else {
                v = (kg < 256) ? *(const float4*)(g_u + m * 256 + kg)
                               : *(const float4*)(pA1 + m * 128 + (kg - 256));
            }
            As[lk + 0][ml] = v.x;
            As[lk + 1][ml] = v.y;
            As[lk + 2][ml] = v.z;
            As[lk + 3][ml] = v.w;
        }
#pragma unroll
        for (int h = 0; h < 2; h++) {
            int nl = lm + h * 64;
            size_t n = (size_t)(n0 + nl);
            float4 v;
            if constexpr (MODE == 0) {
                v = *(const float4*)(pB0 + n * 256 + kg);
            } else if constexpr (MODE == 1) {
                v = *(const float4*)(pB0 + n * 512 + kg);
            } else {
                v = (kg < 256) ? *(const float4*)(pB0 + n * 256 + kg)
                               : *(const float4*)(pB1 + n * 128 + (kg - 256));
            }
            Bs[lk + 0][nl] = v.x;
            Bs[lk + 1][nl] = v.y;
            Bs[lk + 2][nl] = v.z;
            Bs[lk + 3][nl] = v.w;
        }
        __syncthreads();
#pragma unroll
        for (int kk = 0; kk < 16; kk++) {
            ulonglong2 a01 = *(const ulonglong2*)&As[kk][ty * 8];
            ulonglong2 a23 = *(const ulonglong2*)&As[kk][ty * 8 + 4];
            float4 b0v = *(const float4*)&Bs[kk][tx * 8];
            float4 b1v = *(const float4*)&Bs[kk][tx * 8 + 4];
            unsigned long long a2[4] = {a01.x, a01.y, a23.x, a23.y};
            float bn[8] = {b0v.x, b0v.y, b0v.z, b0v.w, b1v.x, b1v.y, b1v.z, b1v.w};
#pragma unroll
            for (int n = 0; n < 8; n++) {
                unsigned long long bb = bcast2(bn[n]);
#pragma unroll
                for (int mp = 0; mp < 4; mp++) fma2(acc[mp][n], a2[mp], bb);
            }
        }
        __syncthreads();
    }

#pragma unroll
    for (int r = 0; r < 8; r++) {
        float c[8];
#pragma unroll
        for (int n = 0; n < 8; n++) {
            float2 v = unpk(acc[r >> 1][n]);
            c[n] = (r & 1) ? v.y : v.x;
        }
        size_t m = (size_t)(m0 + ty * 8 + r);
        size_t col = (size_t)(n0 + tx * 8);

        if constexpr (MODE == 0) {
            size_t base = m * 512 + col;
            *(float4*)(g_h + base) = make_float4(fmaxf(c[0], 0.f), fmaxf(c[1], 0.f),
                                                 fmaxf(c[2], 0.f), fmaxf(c[3], 0.f));
            *(float4*)(g_h + base + 4) = make_float4(fmaxf(c[4], 0.f), fmaxf(c[5], 0.f),
                                                     fmaxf(c[6], 0.f), fmaxf(c[7], 0.f));
        } else if constexpr (MODE == 1) {
            size_t base = m * 256 + col;
            float u[8];
#pragma unroll
            for (int n = 0; n < 8; n++) u[n] = fmaxf(c[n], 0.f);
            *(float4*)(g_u + base) = make_float4(u[0], u[1], u[2], u[3]);
            *(float4*)(g_u + base + 4) = make_float4(u[4], u[5], u[6], u[7]);
            float4 mn0 = *(const float4*)(pUmin + base);
            float4 mn1 = *(const float4*)(pUmin + base + 4);
            float4 mx0 = *(const float4*)(pUmax + base);
            float4 mx1 = *(const float4*)(pUmax + base + 4);
            *(float4*)(out + SUMIN_OFF + base) =
                make_float4(fmaxf(mn0.x - u[0], 0.f), fmaxf(mn0.y - u[1], 0.f),
                            fmaxf(mn0.z - u[2], 0.f), fmaxf(mn0.w - u[3], 0.f));
            *(float4*)(out + SUMIN_OFF + base + 4) =
                make_float4(fmaxf(mn1.x - u[4], 0.f), fmaxf(mn1.y - u[5], 0.f),
                            fmaxf(mn1.z - u[6], 0.f), fmaxf(mn1.w - u[7], 0.f));
            *(float4*)(out + SUMAX_OFF + base) =
                make_float4(fmaxf(u[0] - mx0.x, 0.f), fmaxf(u[1] - mx0.y, 0.f),
                            fmaxf(u[2] - mx0.z, 0.f), fmaxf(u[3] - mx0.w, 0.f));
            *(float4*)(out + SUMAX_OFF + base + 4) =
                make_float4(fmaxf(u[4] - mx1.x, 0.f), fmaxf(u[5] - mx1.y, 0.f),
                            fmaxf(u[6] - mx1.z, 0.f), fmaxf(u[7] - mx1.w, 0.f));
        } else {
            size_t base = m * 256 + col;
            *(float4*)(out + X_OFF + base) = make_float4(c[0], c[1], c[2], c[3]);
            *(float4*)(out + X_OFF + base + 4) = make_float4(c[4], c[5], c[6], c[7]);
        }
    }
}

// ---------------- Cluster-resident sequential scan ----------------
// 64 clusters x 2 CTAs (grid 128), 256 threads/CTA, 4 batch rows per cluster.
// CTA rank r holds A_eff columns [128r,128r+128) in smem, computes that half of
// x_t, writes it to its own and peer's next-state buffer (DSMEM), one
// barrier.cluster per step (double-buffered state makes one sync sufficient).
struct ScanSmem {
    float A[256][128];                     // 128 KB: A[j][il] = A_eff[j][128*rank+il]
    ulonglong2 xs2[2][256];                // 16 KB: double-buffered state, rowpairs packed
    unsigned long long part[4][64][2][2];  // 8 KB: [jj][cp][cip][rowpair]
};

__global__ void __launch_bounds__(256, 1) __cluster_dims__(2, 1, 1)
scan_kernel(const float* __restrict__ x0, const float* __restrict__ XMIN,
            const float* __restrict__ XMAX, float* __restrict__ out) {
    extern __shared__ char smem_raw[];
    ScanSmem* S = reinterpret_cast<ScanSmem*>(smem_raw);
    int tid = threadIdx.x;
    unsigned rank = ctarank();
    int b0 = (int)(blockIdx.x >> 1) * 4;

    // Load this CTA's half of A_eff into smem (128 KB, coalesced float4)
#pragma unroll
    for (int it = 0; it < 32; it++) {
        int idx4 = tid + it * 256;          // 0..8191
        int j = idx4 >> 5;                  // 32 float4 per row
        int c4 = idx4 & 31;
        float4 v = *(const float4*)(g_Aeff + (size_t)j * 256 + rank * 128 + c4 * 4);
        *(float4*)(&S->A[j][c4 * 4]) = v;
    }
    // Initial state (full x, both row-pairs packed)
    {
        int j = tid;
        float a0 = x0[(b0 + 0) * 256 + j];
        float a1 = x0[(b0 + 1) * 256 + j];
        float a2 = x0[(b0 + 2) * 256 + j];
        float a3 = x0[(b0 + 3) * 256 + j];
        S->xs2[0][j] = make_ulonglong2(pk2(a0, a1), pk2(a2, a3));
    }
    __syncthreads();

    const int jj = tid >> 6;        // j-block 0..3
    const int cp = tid & 63;        // local column pair 0..63
    const int il = tid & 127;       // finalize: local column
    const int h  = tid >> 7;        // finalize: rowpair
    const int gcol = (int)rank * 128 + il;

    // Prefetch step-0 operands
    float pf_d0, pf_d1, pf_mn0, pf_mn1, pf_mx0, pf_mx1;
    {
        size_t idx0 = ((size_t)(b0 + 2 * h)) * 256 + gcol;
        pf_d0 = out[X_OFF + idx0];        pf_d1 = out[X_OFF + idx0 + 256];
        pf_mn0 = XMIN[idx0];              pf_mn1 = XMIN[idx0 + 256];
        pf_mx0 = XMAX[idx0];              pf_mx1 = XMAX[idx0 + 256];
    }

    for (int t = 0; t < 512; t++) {
        int p = t & 1;
        unsigned long long a00 = 0, a01 = 0, a10 = 0, a11 = 0;
        const ulonglong2* xb = S->xs2[p];
        const float2* Arow = (const float2*)&S->A[jj * 64][0] + cp;
#pragma unroll 8
        for (int it = 0; it < 64; it++) {
            int j = jj * 64 + it;
            float2 a = Arow[(size_t)it * 64];
            ulonglong2 xv = xb[j];
            unsigned long long b0p = bcast2(a.x), b1p = bcast2(a.y);
            fma2(a00, b0p, xv.x);
            fma2(a01, b0p, xv.y);
            fma2(a10, b1p, xv.x);
            fma2(a11, b1p, xv.y);
        }
        S->part[jj][cp][0][0] = a00;
        S->part[jj][cp][0][1] = a01;
        S->part[jj][cp][1][0] = a10;
        S->part[jj][cp][1][1] = a11;
        __syncthreads();

        // Finalize: thread handles (column il, rows 2h,2h+1)
        int cp2 = il >> 1, cip = il & 1;
        unsigned long long s = S->part[0][cp2][cip][h];
        add2(s, S->part[1][cp2][cip][h]);
        add2(s, S->part[2][cp2][cip][h]);
        add2(s, S->part[3][cp2][cip][h]);
        float2 sv = unpk(s);
        float v0 = sv.x + pf_d0;
        float v1 = sv.y + pf_d1;

        size_t idx = ((size_t)t * 256 + b0 + 2 * h) * 256 + gcol;
        out[X_OFF + idx]           = v0;
        out[X_OFF + idx + 256]     = v1;
        out[SXMIN_OFF + idx]       = fmaxf(pf_mn0 - v0, 0.f);
        out[SXMIN_OFF + idx + 256] = fmaxf(pf_mn1 - v1, 0.f);
        out[SXMAX_OFF + idx]       = fmaxf(v0 - pf_mx0, 0.f);
        out[SXMAX_OFF + idx + 256] = fmaxf(v1 - pf_mx1, 0.f);
        if (gcol == 255) {
            out[Y_OFF + (size_t)t * 256 + b0 + 2 * h]     = v0;
            out[Y_OFF + (size_t)t * 256 + b0 + 2 * h + 1] = v1;
        }

        // Next-state write: local + peer (DSMEM)
        unsigned long long xn = pk2(v0, v1);
        unsigned long long* dst =
            (h == 0) ? &S->xs2[p ^ 1][gcol].x : &S->xs2[p ^ 1][gcol].y;
        *dst = xn;
        unsigned laddr = smem_u32(dst);
        unsigned raddr;
        asm("mapa.shared::cluster.u32 %0, %1, %2;" : "=r"(raddr) : "r"(laddr), "r"(rank ^ 1u));
        asm volatile("st.shared::cluster.u64 [%0], %1;" :: "r"(raddr), "l"(xn) : "memory");

        // Prefetch next step's operands (clamped; t=511 value unused)
        int tn = (t < 511) ? t + 1 : 511;
        size_t idxn = ((size_t)tn * 256 + b0 + 2 * h) * 256 + gcol;
        pf_d0 = out[X_OFF + idxn];        pf_d1 = out[X_OFF + idxn + 256];
        pf_mn0 = XMIN[idxn];              pf_mn1 = XMIN[idxn + 256];
        pf_mx0 = XMAX[idxn];              pf_mx1 = XMAX[idxn + 256];

        asm volatile("barrier.cluster.arrive.aligned;" ::: "memory");
        asm volatile("barrier.cluster.wait.aligned;" ::: "memory");
    }
}

// ---------------- launch ----------------
extern "C" void kernel_launch(void* const* d_in, const int* in_sizes, int n_in,
                              void* d_out, int out_size) {
    const float* x      = (const float*)d_in[0];
    const float* M_flow = (const float*)d_in[1];
    const float* DT     = (const float*)d_in[2];
    const float* D      = (const float*)d_in[3];
    const float* XMIN   = (const float*)d_in[4];
    const float* XMAX   = (const float*)d_in[5];
    const float* UMIN   = (const float*)d_in[6];
    const float* UMAX   = (const float*)d_in[7];
    const float* A_w    = (const float*)d_in[8];
    const float* A_sc   = (const float*)d_in[9];
    const float* B_W    = (const float*)d_in[10];
    const float* E_W    = (const float*)d_in[11];
    const float* hf1_W  = (const float*)d_in[12];
    const float* hf2_W  = (const float*)d_in[13];
    float* out = (float*)d_out;

    build_aeff_kernel<<<256, 256>>>(A_w, A_sc);
    gemm_kernel<0><<<dim3(4, 1024), 256>>>(M_flow, DT, hf1_W, nullptr, nullptr, nullptr, out);
    gemm_kernel<1><<<dim3(2, 1024), 256>>>(nullptr, nullptr, hf2_W, nullptr, UMIN, UMAX, out);
    gemm_kernel<2><<<dim3(2, 1024), 256>>>(nullptr, D, B_W, E_W, nullptr, nullptr, out);

    static_assert(sizeof(ScanSmem) <= 160 * 1024, "smem overflow");
    cudaFuncSetAttribute(scan_kernel, cudaFuncAttributeMaxDynamicSharedMemorySize,
                         (int)sizeof(ScanSmem));
    scan_kernel<<<128, 256, sizeof(ScanSmem)>>>(x, XMIN, XMAX, out);
}

// round 6
// speedup vs baseline: 2.4616x; 1.5835x over previous
#include <cuda_runtime.h>
#include <cuda_bf16.h>
#include <cstdint>
#include <cstddef>

// T=512, B=256, NX=256, NU=256, ND=128, NM=128, NDT=128, NH=512, M=T*B=131072
static constexpr size_t X_OFF     = 0;
static constexpr size_t Y_OFF     = 33554432;
static constexpr size_t SXMIN_OFF = 33685504;
static constexpr size_t SXMAX_OFF = 67239936;
static constexpr size_t SUMIN_OFF = 100794368;
static constexpr size_t SUMAX_OFF = 134348800;

__device__ float g_Aeff[256 * 256];
__device__ __nv_bfloat16 g_h_hi[(size_t)131072 * 512];
__device__ __nv_bfloat16 g_h_lo[(size_t)131072 * 512];
__device__ __nv_bfloat16 g_u_hi[(size_t)131072 * 256];
__device__ __nv_bfloat16 g_u_lo[(size_t)131072 * 256];

// ---------------- f32x2 helpers (scan) ----------------
__device__ __forceinline__ unsigned long long pk2(float a, float b) {
    unsigned long long r;
    asm("mov.b64 %0, {%1, %2};" : "=l"(r) : "r"(__float_as_uint(a)), "r"(__float_as_uint(b)));
    return r;
}
__device__ __forceinline__ unsigned long long bcast2(float v) {
    unsigned long long r;
    unsigned u = __float_as_uint(v);
    asm("mov.b64 %0, {%1, %1};" : "=l"(r) : "r"(u));
    return r;
}
__device__ __forceinline__ void fma2(unsigned long long& d, unsigned long long a, unsigned long long b) {
    asm("fma.rn.f32x2 %0, %1, %2, %0;" : "+l"(d) : "l"(a), "l"(b));
}
__device__ __forceinline__ void add2(unsigned long long& d, unsigned long long a) {
    asm("add.rn.f32x2 %0, %0, %1;" : "+l"(d) : "l"(a));
}
__device__ __forceinline__ float2 unpk(unsigned long long v) {
    unsigned lo, hi;
    asm("mov.b64 {%0, %1}, %2;" : "=r"(lo), "=r"(hi) : "l"(v));
    return make_float2(__uint_as_float(lo), __uint_as_float(hi));
}
__device__ __forceinline__ unsigned smem_u32(const void* p) {
    unsigned r;
    asm("{ .reg .u64 t; cvta.to.shared.u64 t, %1; cvt.u32.u64 %0, t; }" : "=r"(r) : "l"(p));
    return r;
}
__device__ __forceinline__ unsigned ctarank() {
    unsigned r;
    asm("mov.u32 %0, %%cluster_ctarank;" : "=r"(r));
    return r;
}

// ---------------- mma.sync / ldmatrix helpers (baseline PTX) ----------------
__device__ __forceinline__ void ldsm4(unsigned* r, uint32_t addr) {
    asm volatile("ldmatrix.sync.aligned.m8n8.x4.shared.b16 {%0,%1,%2,%3}, [%4];"
                 : "=r"(r[0]), "=r"(r[1]), "=r"(r[2]), "=r"(r[3]) : "r"(addr));
}
__device__ __forceinline__ void mma_bf16(float* d, const unsigned* a, unsigned b0, unsigned b1) {
    asm volatile(
        "mma.sync.aligned.m16n8k16.row.col.f32.bf16.bf16.f32 "
        "{%0,%1,%2,%3}, {%4,%5,%6,%7}, {%8,%9}, {%0,%1,%2,%3};"
        : "+f"(d[0]), "+f"(d[1]), "+f"(d[2]), "+f"(d[3])
        : "r"(a[0]), "r"(a[1]), "r"(a[2]), "r"(a[3]), "r"(b0), "r"(b1));
}

// convert 8 fp32 -> 8 bf16 hi + 8 bf16 lo (packed as uint4 each)
__device__ __forceinline__ void cvt8(const float* f, uint4& hi4, uint4& lo4) {
    unsigned h[4], l[4];
#pragma unroll
    for (int i = 0; i < 4; i++) {
        __nv_bfloat16 h0 = __float2bfloat16_rn(f[2 * i]);
        __nv_bfloat16 h1 = __float2bfloat16_rn(f[2 * i + 1]);
        __nv_bfloat16 l0 = __float2bfloat16_rn(f[2 * i] - __bfloat162float(h0));
        __nv_bfloat16 l1 = __float2bfloat16_rn(f[2 * i + 1] - __bfloat162float(h1));
        h[i] = (unsigned)__bfloat16_as_ushort(h0) | ((unsigned)__bfloat16_as_ushort(h1) << 16);
        l[i] = (unsigned)__bfloat16_as_ushort(l0) | ((unsigned)__bfloat16_as_ushort(l1) << 16);
    }
    hi4 = make_uint4(h[0], h[1], h[2], h[3]);
    lo4 = make_uint4(l[0], l[1], l[2], l[3]);
}
__device__ __forceinline__ unsigned pack_bf16x2(float a, float b) {
    __nv_bfloat16 x = __float2bfloat16_rn(a), y = __float2bfloat16_rn(b);
    return (unsigned)__bfloat16_as_ushort(x) | ((unsigned)__bfloat16_as_ushort(y) << 16);
}

// ---------------- A_eff prep ----------------
__global__ void build_aeff_kernel(const float* __restrict__ Aw, const float* __restrict__ Asc) {
    int r = blockIdx.x, c = threadIdx.x;
    __shared__ float red[256];
    float w = Aw[r * 256 + c];
    red[c] = w;
    __syncthreads();
#pragma unroll
    for (int s = 128; s > 0; s >>= 1) {
        if (c < s) red[c] = fmaxf(red[c], red[c + s]);
        __syncthreads();
    }
    float mx = red[0];
    __syncthreads();
    float e = expf(w - mx);
    red[c] = e;
    __syncthreads();
#pragma unroll
    for (int s = 128; s > 0; s >>= 1) {
        if (c < s) red[c] += red[c + s];
        __syncthreads();
    }
    float p = e / red[0];
    float sg = 1.f / (1.f + expf(-Asc[r * 256 + c]));
    g_Aeff[c * 256 + r] = (1.f - 0.1f * sg) * p;
}

// ---------------- HMMA GEMM, C = A * B^T, bf16 hi/lo split ----------------
static constexpr int SROW = 144;  // bytes per smem row (64 bf16 + 8 pad)

template <int MODE>
__global__ void __launch_bounds__(256, 2)
gemm_mma_kernel(const float* __restrict__ pA0, const float* __restrict__ pA1,
                const float* __restrict__ pB0, const float* __restrict__ pB1,
                const float* __restrict__ pUmin, const float* __restrict__ pUmax,
                float* __restrict__ out) {
    constexpr int K = (MODE == 0) ? 256 : (MODE == 1) ? 512 : 384;
    constexpr int NCH = K / 64;
    constexpr uint32_t AHI = 0, ALO = 18432, BHI = 36864, BLO = 55296;

    extern __shared__ char smem[];
    uint32_t sb = smem_u32(smem);

    int tid = threadIdx.x;
    int lane = tid & 31;
    int wid = tid >> 5;
    int wm = wid & 3;            // M warp group (32 rows)
    int wn = wid >> 2;           // N warp group (64 cols)
    int m0 = blockIdx.y * 128;
    int n0 = blockIdx.x * 128;

    uint32_t a_off = (uint32_t)((lane & 15) * SROW + ((lane >> 4) << 3) * 2);
    uint32_t b_off = (uint32_t)((((lane & 7) | ((lane >> 4) << 3))) * SROW +
                                (((lane >> 3) & 1) << 3) * 2);

    float d[2][8][4];
#pragma unroll
    for (int i = 0; i < 2; i++)
#pragma unroll
        for (int j = 0; j < 8; j++)
#pragma unroll
            for (int k = 0; k < 4; k++) d[i][j][k] = 0.f;

    for (int kc = 0; kc < NCH; kc++) {
        int k0 = kc * 64;
        __syncthreads();

        // ---- stage A tile (128 x 64) ----
        if constexpr (MODE == 0) {
#pragma unroll
            for (int it = 0; it < 4; it++) {
                int g = it * 256 + tid;
                int row = g >> 3, c8 = g & 7;
                int k = k0 + c8 * 8;
                size_t m = (size_t)(m0 + row);
                const float* src = (k < 128) ? pA0 + m * 128 + k : pA1 + m * 128 + (k - 128);
                float f[8];
                *(float4*)f = *(const float4*)src;
                *(float4*)(f + 4) = *(const float4*)(src + 4);
                uint4 hv, lv;
                cvt8(f, hv, lv);
                uint32_t off = (uint32_t)(row * SROW + c8 * 16);
                *(uint4*)(smem + AHI + off) = hv;
                *(uint4*)(smem + ALO + off) = lv;
            }
        } else if constexpr (MODE == 1) {
#pragma unroll
            for (int it = 0; it < 4; it++) {
                int g = it * 256 + tid;
                int row = g >> 3, c8 = g & 7;
                size_t gi = (size_t)(m0 + row) * 512 + k0 + c8 * 8;
                uint32_t off = (uint32_t)(row * SROW + c8 * 16);
                *(uint4*)(smem + AHI + off) = *(const uint4*)(g_h_hi + gi);
                *(uint4*)(smem + ALO + off) = *(const uint4*)(g_h_lo + gi);
            }
        } else {
            if (k0 < 256) {
#pragma unroll
                for (int it = 0; it < 4; it++) {
                    int g = it * 256 + tid;
                    int row = g >> 3, c8 = g & 7;
                    size_t gi = (size_t)(m0 + row) * 256 + k0 + c8 * 8;
                    uint32_t off = (uint32_t)(row * SROW + c8 * 16);
                    *(uint4*)(smem + AHI + off) = *(const uint4*)(g_u_hi + gi);
                    *(uint4*)(smem + ALO + off) = *(const uint4*)(g_u_lo + gi);
                }
            } else {
#pragma unroll
                for (int it = 0; it < 4; it++) {
                    int g = it * 256 + tid;
                    int row = g >> 3, c8 = g & 7;
                    int k = k0 - 256 + c8 * 8;
                    const float* src = pA1 + (size_t)(m0 + row) * 128 + k;
                    float f[8];
                    *(float4*)f = *(const float4*)src;
                    *(float4*)(f + 4) = *(const float4*)(src + 4);
                    uint4 hv, lv;
                    cvt8(f, hv, lv);
                    uint32_t off = (uint32_t)(row * SROW + c8 * 16);
                    *(uint4*)(smem + AHI + off) = hv;
                    *(uint4*)(smem + ALO + off) = lv;
                }
            }
        }
        // ---- stage B tile (128 x 64) fp32 -> hi/lo ----
#pragma unroll
        for (int it = 0; it < 4; it++) {
            int g = it * 256 + tid;
            int row = g >> 3, c8 = g & 7;
            int k = k0 + c8 * 8;
            size_t n = (size_t)(n0 + row);
            const float* src;
            if constexpr (MODE == 0) {
                src = pB0 + n * 256 + k;
            } else if constexpr (MODE == 1) {
                src = pB0 + n * 512 + k;
            } else {
                src = (k < 256) ? pB0 + n * 256 + k : pB1 + n * 128 + (k - 256);
            }
            float f[8];
            *(float4*)f = *(const float4*)src;
            *(float4*)(f + 4) = *(const float4*)(src + 4);
            uint4 hv, lv;
            cvt8(f, hv, lv);
            uint32_t off = (uint32_t)(row * SROW + c8 * 16);
            *(uint4*)(smem + BHI + off) = hv;
            *(uint4*)(smem + BLO + off) = lv;
        }
        __syncthreads();

        // ---- mma over 4 k16 steps ----
#pragma unroll
        for (int ks = 0; ks < 4; ks++) {
            unsigned ah[2][4], al[2][4];
#pragma unroll
            for (int mt = 0; mt < 2; mt++) {
                uint32_t base = sb + (uint32_t)((wm * 32 + mt * 16) * SROW + ks * 32) + a_off;
                ldsm4(ah[mt], base + AHI);
                ldsm4(al[mt], base + ALO);
            }
#pragma unroll
            for (int nt = 0; nt < 4; nt++) {
                unsigned bh[4], bl[4];
                uint32_t base = sb + (uint32_t)((wn * 64 + nt * 16) * SROW + ks * 32) + b_off;
                ldsm4(bh, base + BHI);
                ldsm4(bl, base + BLO);
#pragma unroll
                for (int mt = 0; mt < 2; mt++) {
#pragma unroll
                    for (int nn = 0; nn < 2; nn++) {
                        float* dd = d[mt][nt * 2 + nn];
                        mma_bf16(dd, ah[mt], bh[2 * nn], bh[2 * nn + 1]);
                        mma_bf16(dd, ah[mt], bl[2 * nn], bl[2 * nn + 1]);
                        mma_bf16(dd, al[mt], bh[2 * nn], bh[2 * nn + 1]);
                    }
                }
            }
        }
    }

    // ---- epilogue ----
    int g = lane >> 2, q = lane & 3;
#pragma unroll
    for (int mt = 0; mt < 2; mt++) {
        int r0 = m0 + wm * 32 + mt * 16 + g;
#pragma unroll
        for (int j = 0; j < 8; j++) {
            int c = n0 + wn * 64 + j * 8 + 2 * q;
            float* dd = d[mt][j];
#pragma unroll
            for (int h = 0; h < 2; h++) {
                size_t m = (size_t)(r0 + h * 8);
                float v0 = dd[2 * h], v1 = dd[2 * h + 1];
                if constexpr (MODE == 0) {
                    float u0 = fmaxf(v0, 0.f), u1 = fmaxf(v1, 0.f);
                    size_t idx = m * 512 + c;
                    __nv_bfloat16 h0 = __float2bfloat16_rn(u0);
                    __nv_bfloat16 h1 = __float2bfloat16_rn(u1);
                    unsigned hp = (unsigned)__bfloat16_as_ushort(h0) |
                                  ((unsigned)__bfloat16_as_ushort(h1) << 16);
                    unsigned lp = pack_bf16x2(u0 - __bfloat162float(h0),
                                              u1 - __bfloat162float(h1));
                    *(unsigned*)(g_h_hi + idx) = hp;
                    *(unsigned*)(g_h_lo + idx) = lp;
                } else if constexpr (MODE == 1) {
                    float u0 = fmaxf(v0, 0.f), u1 = fmaxf(v1, 0.f);
                    size_t idx = m * 256 + c;
                    __nv_bfloat16 h0 = __float2bfloat16_rn(u0);
                    __nv_bfloat16 h1 = __float2bfloat16_rn(u1);
                    unsigned hp = (unsigned)__bfloat16_as_ushort(h0) |
                                  ((unsigned)__bfloat16_as_ushort(h1) << 16);
                    unsigned lp = pack_bf16x2(u0 - __bfloat162float(h0),
                                              u1 - __bfloat162float(h1));
                    *(unsigned*)(g_u_hi + idx) = hp;
                    *(unsigned*)(g_u_lo + idx) = lp;
                    float2 mn = *(const float2*)(pUmin + idx);
                    float2 mx = *(const float2*)(pUmax + idx);
                    *(float2*)(out + SUMIN_OFF + idx) =
                        make_float2(fmaxf(mn.x - u0, 0.f), fmaxf(mn.y - u1, 0.f));
                    *(float2*)(out + SUMAX_OFF + idx) =
                        make_float2(fmaxf(u0 - mx.x, 0.f), fmaxf(u1 - mx.y, 0.f));
                } else {
                    size_t idx = m * 256 + c;
                    *(float2*)(out + X_OFF + idx) = make_float2(v0, v1);
                }
            }
        }
    }
}

// ---------------- Cluster-resident sequential scan (unchanged from R4) ----------------
struct ScanSmem {
    float A[256][128];
    ulonglong2 xs2[2][256];
    unsigned long long part[4][64][2][2];
};

__global__ void __launch_bounds__(256, 1) __cluster_dims__(2, 1, 1)
scan_kernel(const float* __restrict__ x0, const float* __restrict__ XMIN,
            const float* __restrict__ XMAX, float* __restrict__ out) {
    extern __shared__ char smem_raw[];
    ScanSmem* S = reinterpret_cast<ScanSmem*>(smem_raw);
    int tid = threadIdx.x;
    unsigned rank = ctarank();
    int b0 = (int)(blockIdx.x >> 1) * 4;

#pragma unroll
    for (int it = 0; it < 32; it++) {
        int idx4 = tid + it * 256;
        int j = idx4 >> 5;
        int c4 = idx4 & 31;
        float4 v = *(const float4*)(g_Aeff + (size_t)j * 256 + rank * 128 + c4 * 4);
        *(float4*)(&S->A[j][c4 * 4]) = v;
    }
    {
        int j = tid;
        float a0 = x0[(b0 + 0) * 256 + j];
        float a1 = x0[(b0 + 1) * 256 + j];
        float a2 = x0[(b0 + 2) * 256 + j];
        float a3 = x0[(b0 + 3) * 256 + j];
        S->xs2[0][j] = make_ulonglong2(pk2(a0, a1), pk2(a2, a3));
    }
    __syncthreads();

    const int jj = tid >> 6;
    const int cp = tid & 63;
    const int il = tid & 127;
    const int h  = tid >> 7;
    const int gcol = (int)rank * 128 + il;

    float pf_d0, pf_d1, pf_mn0, pf_mn1, pf_mx0, pf_mx1;
    {
        size_t idx0 = ((size_t)(b0 + 2 * h)) * 256 + gcol;
        pf_d0 = out[X_OFF + idx0];        pf_d1 = out[X_OFF + idx0 + 256];
        pf_mn0 = XMIN[idx0];              pf_mn1 = XMIN[idx0 + 256];
        pf_mx0 = XMAX[idx0];              pf_mx1 = XMAX[idx0 + 256];
    }

    for (int t = 0; t < 512; t++) {
        int p = t & 1;
        unsigned long long a00 = 0, a01 = 0, a10 = 0, a11 = 0;
        const ulonglong2* xb = S->xs2[p];
        const float2* Arow = (const float2*)&S->A[jj * 64][0] + cp;
#pragma unroll 8
        for (int it = 0; it < 64; it++) {
            int j = jj * 64 + it;
            float2 a = Arow[(size_t)it * 64];
            ulonglong2 xv = xb[j];
            unsigned long long b0p = bcast2(a.x), b1p = bcast2(a.y);
            fma2(a00, b0p, xv.x);
            fma2(a01, b0p, xv.y);
            fma2(a10, b1p, xv.x);
            fma2(a11, b1p, xv.y);
        }
        S->part[jj][cp][0][0] = a00;
        S->part[jj][cp][0][1] = a01;
        S->part[jj][cp][1][0] = a10;
        S->part[jj][cp][1][1] = a11;
        __syncthreads();

        int cp2 = il >> 1, cip = il & 1;
        unsigned long long s = S->part[0][cp2][cip][h];
        add2(s, S->part[1][cp2][cip][h]);
        add2(s, S->part[2][cp2][cip][h]);
        add2(s, S->part[3][cp2][cip][h]);
        float2 sv = unpk(s);
        float v0 = sv.x + pf_d0;
        float v1 = sv.y + pf_d1;

        size_t idx = ((size_t)t * 256 + b0 + 2 * h) * 256 + gcol;
        out[X_OFF + idx]           = v0;
        out[X_OFF + idx + 256]     = v1;
        out[SXMIN_OFF + idx]       = fmaxf(pf_mn0 - v0, 0.f);
        out[SXMIN_OFF + idx + 256] = fmaxf(pf_mn1 - v1, 0.f);
        out[SXMAX_OFF + idx]       = fmaxf(v0 - pf_mx0, 0.f);
        out[SXMAX_OFF + idx + 256] = fmaxf(v1 - pf_mx1, 0.f);
        if (gcol == 255) {
            out[Y_OFF + (size_t)t * 256 + b0 + 2 * h]     = v0;
            out[Y_OFF + (size_t)t * 256 + b0 + 2 * h + 1] = v1;
        }

        unsigned long long xn = pk2(v0, v1);
        unsigned long long* dst =
            (h == 0) ? &S->xs2[p ^ 1][gcol].x : &S->xs2[p ^ 1][gcol].y;
        *dst = xn;
        unsigned laddr = smem_u32(dst);
        unsigned raddr;
        asm("mapa.shared::cluster.u32 %0, %1, %2;" : "=r"(raddr) : "r"(laddr), "r"(rank ^ 1u));
        asm volatile("st.shared::cluster.u64 [%0], %1;" :: "r"(raddr), "l"(xn) : "memory");

        int tn = (t < 511) ? t + 1 : 511;
        size_t idxn = ((size_t)tn * 256 + b0 + 2 * h) * 256 + gcol;
        pf_d0 = out[X_OFF + idxn];        pf_d1 = out[X_OFF + idxn + 256];
        pf_mn0 = XMIN[idxn];              pf_mn1 = XMIN[idxn + 256];
        pf_mx0 = XMAX[idxn];              pf_mx1 = XMAX[idxn + 256];

        asm volatile("barrier.cluster.arrive.aligned;" ::: "memory");
        asm volatile("barrier.cluster.wait.aligned;" ::: "memory");
    }
}

// ---------------- launch ----------------
extern "C" void kernel_launch(void* const* d_in, const int* in_sizes, int n_in,
                              void* d_out, int out_size) {
    const float* x      = (const float*)d_in[0];
    const float* M_flow = (const float*)d_in[1];
    const float* DT     = (const float*)d_in[2];
    const float* D      = (const float*)d_in[3];
    const float* XMIN   = (const float*)d_in[4];
    const float* XMAX   = (const float*)d_in[5];
    const float* UMIN   = (const float*)d_in[6];
    const float* UMAX   = (const float*)d_in[7];
    const float* A_w    = (const float*)d_in[8];
    const float* A_sc   = (const float*)d_in[9];
    const float* B_W    = (const float*)d_in[10];
    const float* E_W    = (const float*)d_in[11];
    const float* hf1_W  = (const float*)d_in[12];
    const float* hf2_W  = (const float*)d_in[13];
    float* out = (float*)d_out;

    build_aeff_kernel<<<256, 256>>>(A_w, A_sc);

    const int gsmem = 4 * 128 * SROW;  // 73728
    cudaFuncSetAttribute(gemm_mma_kernel<0>, cudaFuncAttributeMaxDynamicSharedMemorySize, gsmem);
    cudaFuncSetAttribute(gemm_mma_kernel<1>, cudaFuncAttributeMaxDynamicSharedMemorySize, gsmem);
    cudaFuncSetAttribute(gemm_mma_kernel<2>, cudaFuncAttributeMaxDynamicSharedMemorySize, gsmem);

    gemm_mma_kernel<0><<<dim3(4, 1024), 256, gsmem>>>(M_flow, DT, hf1_W, nullptr, nullptr, nullptr, out);
    gemm_mma_kernel<1><<<dim3(2, 1024), 256, gsmem>>>(nullptr, nullptr, hf2_W, nullptr, UMIN, UMAX, out);
    gemm_mma_kernel<2><<<dim3(2, 1024), 256, gsmem>>>(nullptr, D, B_W, E_W, nullptr, nullptr, out);

    cudaFuncSetAttribute(scan_kernel, cudaFuncAttributeMaxDynamicSharedMemorySize,
                         (int)sizeof(ScanSmem));
    scan_kernel<<<128, 256, sizeof(ScanSmem)>>>(x, XMIN, XMAX, out);
}

// round 7
// speedup vs baseline: 3.2960x; 1.3390x over previous
#include <cuda_runtime.h>
#include <cuda_bf16.h>
#include <cstdint>
#include <cstddef>

// T=512, B=256, NX=256, NU=256, ND=128, NM=128, NDT=128, NH=512, M=T*B=131072
static constexpr size_t X_OFF     = 0;
static constexpr size_t Y_OFF     = 33554432;
static constexpr size_t SXMIN_OFF = 33685504;
static constexpr size_t SXMAX_OFF = 67239936;
static constexpr size_t SUMIN_OFF = 100794368;
static constexpr size_t SUMAX_OFF = 134348800;

// Powers: g_P[k][j*256+i] = (A_eff)^(k+1)[j][i]  (x_next[i] = sum_j x[j]*A[j][i])
__device__ float g_P[8 * 65536];
__device__ __nv_bfloat16 g_PT_hi[8 * 65536];  // g_PT[k][n*256+kk] = P_k[kk][n]
__device__ __nv_bfloat16 g_PT_lo[8 * 65536];

__device__ __nv_bfloat16 g_h_hi[(size_t)131072 * 512];
__device__ __nv_bfloat16 g_h_lo[(size_t)131072 * 512];
__device__ __nv_bfloat16 g_u_hi[(size_t)131072 * 256];
__device__ __nv_bfloat16 g_u_lo[(size_t)131072 * 256];

// scratch carved from g_h (used only after gemm1 consumed g_h):
//   g_c[j] (j=0..7): c_{b,j}, rows r=b*256+batch, 16384x256 bf16 hi/lo
static constexpr size_t CSTRIDE = (size_t)16384 * 256;  // 4194304
// g_s: s_b states, rows r=b*256+batch, 16384x256 hi/lo, carved from g_u

// ---------------- helpers ----------------
__device__ __forceinline__ unsigned long long pk2(float a, float b) {
    unsigned long long r;
    asm("mov.b64 %0, {%1, %2};" : "=l"(r) : "r"(__float_as_uint(a)), "r"(__float_as_uint(b)));
    return r;
}
__device__ __forceinline__ unsigned long long bcast2(float v) {
    unsigned long long r;
    unsigned u = __float_as_uint(v);
    asm("mov.b64 %0, {%1, %1};" : "=l"(r) : "r"(u));
    return r;
}
__device__ __forceinline__ void fma2(unsigned long long& d, unsigned long long a, unsigned long long b) {
    asm("fma.rn.f32x2 %0, %1, %2, %0;" : "+l"(d) : "l"(a), "l"(b));
}
__device__ __forceinline__ void add2(unsigned long long& d, unsigned long long a) {
    asm("add.rn.f32x2 %0, %0, %1;" : "+l"(d) : "l"(a));
}
__device__ __forceinline__ float2 unpk(unsigned long long v) {
    unsigned lo, hi;
    asm("mov.b64 {%0, %1}, %2;" : "=r"(lo), "=r"(hi) : "l"(v));
    return make_float2(__uint_as_float(lo), __uint_as_float(hi));
}
__device__ __forceinline__ unsigned smem_u32(const void* p) {
    unsigned r;
    asm("{ .reg .u64 t; cvta.to.shared.u64 t, %1; cvt.u32.u64 %0, t; }" : "=r"(r) : "l"(p));
    return r;
}
__device__ __forceinline__ unsigned ctarank() {
    unsigned r;
    asm("mov.u32 %0, %%cluster_ctarank;" : "=r"(r));
    return r;
}
__device__ __forceinline__ void split1(float v, __nv_bfloat16& h, __nv_bfloat16& l) {
    h = __float2bfloat16_rn(v);
    l = __float2bfloat16_rn(v - __bfloat162float(h));
}
__device__ __forceinline__ void ldsm4(unsigned* r, uint32_t addr) {
    asm volatile("ldmatrix.sync.aligned.m8n8.x4.shared.b16 {%0,%1,%2,%3}, [%4];"
                 : "=r"(r[0]), "=r"(r[1]), "=r"(r[2]), "=r"(r[3]) : "r"(addr));
}
__device__ __forceinline__ void mma_bf16(float* d, const unsigned* a, unsigned b0, unsigned b1) {
    asm volatile(
        "mma.sync.aligned.m16n8k16.row.col.f32.bf16.bf16.f32 "
        "{%0,%1,%2,%3}, {%4,%5,%6,%7}, {%8,%9}, {%0,%1,%2,%3};"
        : "+f"(d[0]), "+f"(d[1]), "+f"(d[2]), "+f"(d[3])
        : "r"(a[0]), "r"(a[1]), "r"(a[2]), "r"(a[3]), "r"(b0), "r"(b1));
}
__device__ __forceinline__ void cvt8(const float* f, uint4& hi4, uint4& lo4) {
    unsigned h[4], l[4];
#pragma unroll
    for (int i = 0; i < 4; i++) {
        __nv_bfloat16 h0, l0, h1, l1;
        split1(f[2 * i], h0, l0);
        split1(f[2 * i + 1], h1, l1);
        h[i] = (unsigned)__bfloat16_as_ushort(h0) | ((unsigned)__bfloat16_as_ushort(h1) << 16);
        l[i] = (unsigned)__bfloat16_as_ushort(l0) | ((unsigned)__bfloat16_as_ushort(l1) << 16);
    }
    hi4 = make_uint4(h[0], h[1], h[2], h[3]);
    lo4 = make_uint4(l[0], l[1], l[2], l[3]);
}
__device__ __forceinline__ unsigned pack_hilo(float a, float b, unsigned& lo_out) {
    __nv_bfloat16 h0, l0, h1, l1;
    split1(a, h0, l0);
    split1(b, h1, l1);
    lo_out = (unsigned)__bfloat16_as_ushort(l0) | ((unsigned)__bfloat16_as_ushort(l1) << 16);
    return (unsigned)__bfloat16_as_ushort(h0) | ((unsigned)__bfloat16_as_ushort(h1) << 16);
}
__device__ __forceinline__ float bf2f(__nv_bfloat16 v) { return __bfloat162float(v); }

// ---------------- A_eff prep (writes g_P[0]) ----------------
__global__ void build_aeff_kernel(const float* __restrict__ Aw, const float* __restrict__ Asc) {
    int r = blockIdx.x, c = threadIdx.x;
    __shared__ float red[256];
    float w = Aw[r * 256 + c];
    red[c] = w;
    __syncthreads();
#pragma unroll
    for (int s = 128; s > 0; s >>= 1) {
        if (c < s) red[c] = fmaxf(red[c], red[c + s]);
        __syncthreads();
    }
    float mx = red[0];
    __syncthreads();
    float e = expf(w - mx);
    red[c] = e;
    __syncthreads();
#pragma unroll
    for (int s = 128; s > 0; s >>= 1) {
        if (c < s) red[c] += red[c + s];
        __syncthreads();
    }
    float p = e / red[0];
    float sg = 1.f / (1.f + expf(-Asc[r * 256 + c]));
    g_P[c * 256 + r] = (1.f - 0.1f * sg) * p;
}

// ---------------- matrix powers: g_P[dst+z] = g_P[lsrc] @ g_P[rfirst+z] ----------------
__global__ void pow_kernel(int lsrc, int rfirst, int dstfirst) {
    int row = blockIdx.x, i = threadIdx.x, z = blockIdx.z;
    const float* L = g_P + (size_t)lsrc * 65536;
    const float* R = g_P + (size_t)(rfirst + z) * 65536;
    float* Cd = g_P + (size_t)(dstfirst + z) * 65536;
    __shared__ float Lrow[256];
    Lrow[i] = L[row * 256 + i];
    __syncthreads();
    float a0 = 0, a1 = 0, a2 = 0, a3 = 0;
#pragma unroll 8
    for (int m = 0; m < 256; m += 4) {
        a0 = fmaf(Lrow[m + 0], R[(m + 0) * 256 + i], a0);
        a1 = fmaf(Lrow[m + 1], R[(m + 1) * 256 + i], a1);
        a2 = fmaf(Lrow[m + 2], R[(m + 2) * 256 + i], a2);
        a3 = fmaf(Lrow[m + 3], R[(m + 3) * 256 + i], a3);
    }
    Cd[row * 256 + i] = (a0 + a1) + (a2 + a3);
}

// ---------------- transpose+split powers: g_PT[k][n*256+kk] = hilo(g_P[k][kk*256+n]) ----
__global__ void transp_kernel() {
    int k = blockIdx.x;               // power index 0..7
    int kt = blockIdx.y * 32;         // kk tile
    int nt = blockIdx.z * 32;         // n tile
    int tx = threadIdx.x, ty = threadIdx.y;  // 32 x 8
    __shared__ float tile[32][33];
    const float* P = g_P + (size_t)k * 65536;
#pragma unroll
    for (int r = 0; r < 4; r++) {
        int kk = kt + ty + r * 8;
        tile[ty + r * 8][tx] = P[kk * 256 + nt + tx];
    }
    __syncthreads();
#pragma unroll
    for (int r = 0; r < 4; r++) {
        int n = nt + ty + r * 8;
        float v = tile[tx][ty + r * 8];
        __nv_bfloat16 h, l;
        split1(v, h, l);
        size_t o = (size_t)k * 65536 + (size_t)n * 256 + kt + tx;
        g_PT_hi[o] = h;
        g_PT_lo[o] = l;
    }
}

// ---------------- HMMA GEMM (MLP + drive), unchanged from R6 ----------------
static constexpr int SROW = 144;

template <int MODE>
__global__ void __launch_bounds__(256, 2)
gemm_mma_kernel(const float* __restrict__ pA0, const float* __restrict__ pA1,
                const float* __restrict__ pB0, const float* __restrict__ pB1,
                const float* __restrict__ pUmin, const float* __restrict__ pUmax,
                float* __restrict__ out) {
    constexpr int K = (MODE == 0) ? 256 : (MODE == 1) ? 512 : 384;
    constexpr int NCH = K / 64;
    constexpr uint32_t AHI = 0, ALO = 18432, BHI = 36864, BLO = 55296;

    extern __shared__ char smem[];
    uint32_t sb = smem_u32(smem);

    int tid = threadIdx.x;
    int lane = tid & 31;
    int wid = tid >> 5;
    int wm = wid & 3;
    int wn = wid >> 2;
    int m0 = blockIdx.y * 128;
    int n0 = blockIdx.x * 128;

    uint32_t a_off = (uint32_t)((lane & 15) * SROW + ((lane >> 4) << 3) * 2);
    uint32_t b_off = (uint32_t)((((lane & 7) | ((lane >> 4) << 3))) * SROW +
                                (((lane >> 3) & 1) << 3) * 2);

    float d[2][8][4];
#pragma unroll
    for (int i = 0; i < 2; i++)
#pragma unroll
        for (int j = 0; j < 8; j++)
#pragma unroll
            for (int k = 0; k < 4; k++) d[i][j][k] = 0.f;

    for (int kc = 0; kc < NCH; kc++) {
        int k0 = kc * 64;
        __syncthreads();

        if constexpr (MODE == 0) {
#pragma unroll
            for (int it = 0; it < 4; it++) {
                int g = it * 256 + tid;
                int row = g >> 3, c8 = g & 7;
                int k = k0 + c8 * 8;
                size_t m = (size_t)(m0 + row);
                const float* src = (k < 128) ? pA0 + m * 128 + k : pA1 + m * 128 + (k - 128);
                float f[8];
                *(float4*)f = *(const float4*)src;
                *(float4*)(f + 4) = *(const float4*)(src + 4);
                uint4 hv, lv;
                cvt8(f, hv, lv);
                uint32_t off = (uint32_t)(row * SROW + c8 * 16);
                *(uint4*)(smem + AHI + off) = hv;
                *(uint4*)(smem + ALO + off) = lv;
            }
        } else if constexpr (MODE == 1) {
#pragma unroll
            for (int it = 0; it < 4; it++) {
                int g = it * 256 + tid;
                int row = g >> 3, c8 = g & 7;
                size_t gi = (size_t)(m0 + row) * 512 + k0 + c8 * 8;
                uint32_t off = (uint32_t)(row * SROW + c8 * 16);
                *(uint4*)(smem + AHI + off) = *(const uint4*)(g_h_hi + gi);
                *(uint4*)(smem + ALO + off) = *(const uint4*)(g_h_lo + gi);
            }
        } else {
            if (k0 < 256) {
#pragma unroll
                for (int it = 0; it < 4; it++) {
                    int g = it * 256 + tid;
                    int row = g >> 3, c8 = g & 7;
                    size_t gi = (size_t)(m0 + row) * 256 + k0 + c8 * 8;
                    uint32_t off = (uint32_t)(row * SROW + c8 * 16);
                    *(uint4*)(smem + AHI + off) = *(const uint4*)(g_u_hi + gi);
                    *(uint4*)(smem + ALO + off) = *(const uint4*)(g_u_lo + gi);
                }
            } else {
#pragma unroll
                for (int it = 0; it < 4; it++) {
                    int g = it * 256 + tid;
                    int row = g >> 3, c8 = g & 7;
                    int k = k0 - 256 + c8 * 8;
                    const float* src = pA1 + (size_t)(m0 + row) * 128 + k;
                    float f[8];
                    *(float4*)f = *(const float4*)src;
                    *(float4*)(f + 4) = *(const float4*)(src + 4);
                    uint4 hv, lv;
                    cvt8(f, hv, lv);
                    uint32_t off = (uint32_t)(row * SROW + c8 * 16);
                    *(uint4*)(smem + AHI + off) = hv;
                    *(uint4*)(smem + ALO + off) = lv;
                }
            }
        }
#pragma unroll
        for (int it = 0; it < 4; it++) {
            int g = it * 256 + tid;
            int row = g >> 3, c8 = g & 7;
            int k = k0 + c8 * 8;
            size_t n = (size_t)(n0 + row);
            const float* src;
            if constexpr (MODE == 0) {
                src = pB0 + n * 256 + k;
            } else if constexpr (MODE == 1) {
                src = pB0 + n * 512 + k;
            } else {
                src = (k < 256) ? pB0 + n * 256 + k : pB1 + n * 128 + (k - 256);
            }
            float f[8];
            *(float4*)f = *(const float4*)src;
            *(float4*)(f + 4) = *(const float4*)(src + 4);
            uint4 hv, lv;
            cvt8(f, hv, lv);
            uint32_t off = (uint32_t)(row * SROW + c8 * 16);
            *(uint4*)(smem + BHI + off) = hv;
            *(uint4*)(smem + BLO + off) = lv;
        }
        __syncthreads();

#pragma unroll
        for (int ks = 0; ks < 4; ks++) {
            unsigned ah[2][4], al[2][4];
#pragma unroll
            for (int mt = 0; mt < 2; mt++) {
                uint32_t base = sb + (uint32_t)((wm * 32 + mt * 16) * SROW + ks * 32) + a_off;
                ldsm4(ah[mt], base + AHI);
                ldsm4(al[mt], base + ALO);
            }
#pragma unroll
            for (int nt = 0; nt < 4; nt++) {
                unsigned bh[4], bl[4];
                uint32_t base = sb + (uint32_t)((wn * 64 + nt * 16) * SROW + ks * 32) + b_off;
                ldsm4(bh, base + BHI);
                ldsm4(bl, base + BLO);
#pragma unroll
                for (int mt = 0; mt < 2; mt++) {
#pragma unroll
                    for (int nn = 0; nn < 2; nn++) {
                        float* dd = d[mt][nt * 2 + nn];
                        mma_bf16(dd, ah[mt], bh[2 * nn], bh[2 * nn + 1]);
                        mma_bf16(dd, ah[mt], bl[2 * nn], bl[2 * nn + 1]);
                        mma_bf16(dd, al[mt], bh[2 * nn], bh[2 * nn + 1]);
                    }
                }
            }
        }
    }

    int g = lane >> 2, q = lane & 3;
#pragma unroll
    for (int mt = 0; mt < 2; mt++) {
        int r0 = m0 + wm * 32 + mt * 16 + g;
#pragma unroll
        for (int j = 0; j < 8; j++) {
            int c = n0 + wn * 64 + j * 8 + 2 * q;
            float* dd = d[mt][j];
#pragma unroll
            for (int h = 0; h < 2; h++) {
                size_t m = (size_t)(r0 + h * 8);
                float v0 = dd[2 * h], v1 = dd[2 * h + 1];
                if constexpr (MODE == 0) {
                    float u0 = fmaxf(v0, 0.f), u1 = fmaxf(v1, 0.f);
                    size_t idx = m * 512 + c;
                    unsigned lp, hp = pack_hilo(u0, u1, lp);
                    *(unsigned*)(g_h_hi + idx) = hp;
                    *(unsigned*)(g_h_lo + idx) = lp;
                } else if constexpr (MODE == 1) {
                    float u0 = fmaxf(v0, 0.f), u1 = fmaxf(v1, 0.f);
                    size_t idx = m * 256 + c;
                    unsigned lp, hp = pack_hilo(u0, u1, lp);
                    *(unsigned*)(g_u_hi + idx) = hp;
                    *(unsigned*)(g_u_lo + idx) = lp;
                    float2 mn = *(const float2*)(pUmin + idx);
                    float2 mx = *(const float2*)(pUmax + idx);
                    *(float2*)(out + SUMIN_OFF + idx) =
                        make_float2(fmaxf(mn.x - u0, 0.f), fmaxf(mn.y - u1, 0.f));
                    *(float2*)(out + SUMAX_OFF + idx) =
                        make_float2(fmaxf(u0 - mx.x, 0.f), fmaxf(u1 - mx.y, 0.f));
                } else {
                    size_t idx = m * 256 + c;
                    *(float2*)(out + X_OFF + idx) = make_float2(v0, v1);
                }
            }
        }
    }
}

// ---------------- c0 init: g_c[0] = drive at t=8b (hi/lo) ----------------
__global__ void c0init_kernel(const float* __restrict__ out) {
    int m = blockIdx.x;        // 0..16383 = b*256+batch
    int col = threadIdx.x;
    int b = m >> 8, batch = m & 255;
    size_t xidx = (((size_t)(8 * b) * 256) + batch) * 256 + col;
    float v = out[X_OFF + xidx];
    __nv_bfloat16 h, l;
    split1(v, h, l);
    size_t ci = (size_t)m * 256 + col;
    g_h_hi[ci] = h;
    g_h_lo[ci] = l;
}

// ---------------- block-scan GEMMs: csweep (EPI=0) / reconstruct (EPI=1) ----------------
// C[m][n] = sum_k Aop[m][k] * PT[j][n*256+k], M=16384, N=256, K=256.
template <int EPI>
__global__ void __launch_bounds__(256, 2)
blockscan_gemm(int jparam, const float* __restrict__ XMIN, const float* __restrict__ XMAX,
               float* __restrict__ out) {
    constexpr int NCH = 4;
    constexpr uint32_t AHI = 0, ALO = 18432, BHI = 36864, BLO = 55296;

    extern __shared__ char smem[];
    uint32_t sb = smem_u32(smem);

    int tid = threadIdx.x;
    int lane = tid & 31;
    int wid = tid >> 5;
    int wm = wid & 3;
    int wn = wid >> 2;
    int m0 = blockIdx.y * 128;
    int n0 = blockIdx.x * 128;
    int j = (EPI == 0) ? jparam : (int)blockIdx.z;

    // A operand: csweep -> g_c[j-1]; recon -> g_s (in g_u region)
    const __nv_bfloat16* Ahi;
    const __nv_bfloat16* Alo;
    if constexpr (EPI == 0) {
        Ahi = g_h_hi + (size_t)(j - 1) * CSTRIDE;
        Alo = g_h_lo + (size_t)(j - 1) * CSTRIDE;
    } else {
        Ahi = g_u_hi;
        Alo = g_u_lo;
    }
    const __nv_bfloat16* Bhi = g_PT_hi + (size_t)((EPI == 0) ? 0 : j) * 65536;
    const __nv_bfloat16* Blo = g_PT_lo + (size_t)((EPI == 0) ? 0 : j) * 65536;

    uint32_t a_off = (uint32_t)((lane & 15) * SROW + ((lane >> 4) << 3) * 2);
    uint32_t b_off = (uint32_t)((((lane & 7) | ((lane >> 4) << 3))) * SROW +
                                (((lane >> 3) & 1) << 3) * 2);

    float d[2][8][4];
#pragma unroll
    for (int i = 0; i < 2; i++)
#pragma unroll
        for (int jq = 0; jq < 8; jq++)
#pragma unroll
            for (int k = 0; k < 4; k++) d[i][jq][k] = 0.f;

    for (int kc = 0; kc < NCH; kc++) {
        int k0 = kc * 64;
        __syncthreads();
#pragma unroll
        for (int it = 0; it < 4; it++) {
            int g = it * 256 + tid;
            int row = g >> 3, c8 = g & 7;
            size_t gi = (size_t)(m0 + row) * 256 + k0 + c8 * 8;
            uint32_t off = (uint32_t)(row * SROW + c8 * 16);
            *(uint4*)(smem + AHI + off) = *(const uint4*)(Ahi + gi);
            *(uint4*)(smem + ALO + off) = *(const uint4*)(Alo + gi);
        }
#pragma unroll
        for (int it = 0; it < 4; it++) {
            int g = it * 256 + tid;
            int row = g >> 3, c8 = g & 7;
            size_t bi = (size_t)(n0 + row) * 256 + k0 + c8 * 8;
            uint32_t off = (uint32_t)(row * SROW + c8 * 16);
            *(uint4*)(smem + BHI + off) = *(const uint4*)(Bhi + bi);
            *(uint4*)(smem + BLO + off) = *(const uint4*)(Blo + bi);
        }
        __syncthreads();

#pragma unroll
        for (int ks = 0; ks < 4; ks++) {
            unsigned ah[2][4], al[2][4];
#pragma unroll
            for (int mt = 0; mt < 2; mt++) {
                uint32_t base = sb + (uint32_t)((wm * 32 + mt * 16) * SROW + ks * 32) + a_off;
                ldsm4(ah[mt], base + AHI);
                ldsm4(al[mt], base + ALO);
            }
#pragma unroll
            for (int nt = 0; nt < 4; nt++) {
                unsigned bh[4], bl[4];
                uint32_t base = sb + (uint32_t)((wn * 64 + nt * 16) * SROW + ks * 32) + b_off;
                ldsm4(bh, base + BHI);
                ldsm4(bl, base + BLO);
#pragma unroll
                for (int mt = 0; mt < 2; mt++) {
#pragma unroll
                    for (int nn = 0; nn < 2; nn++) {
                        float* dd = d[mt][nt * 2 + nn];
                        mma_bf16(dd, ah[mt], bh[2 * nn], bh[2 * nn + 1]);
                        mma_bf16(dd, ah[mt], bl[2 * nn], bl[2 * nn + 1]);
                        mma_bf16(dd, al[mt], bh[2 * nn], bh[2 * nn + 1]);
                    }
                }
            }
        }
    }

    int g = lane >> 2, q = lane & 3;
#pragma unroll
    for (int mt = 0; mt < 2; mt++) {
        int r0 = m0 + wm * 32 + mt * 16 + g;
#pragma unroll
        for (int jq = 0; jq < 8; jq++) {
            int c = n0 + wn * 64 + jq * 8 + 2 * q;
            float* dd = d[mt][jq];
#pragma unroll
            for (int h = 0; h < 2; h++) {
                int m = r0 + h * 8;
                float v0 = dd[2 * h], v1 = dd[2 * h + 1];
                int b = m >> 8, batch = m & 255;
                int t = 8 * b + j;
                size_t xidx = (((size_t)t * 256) + batch) * 256 + c;
                size_t ci = (size_t)j * CSTRIDE + (size_t)m * 256 + c;
                if constexpr (EPI == 0) {
                    float2 dr = *(const float2*)(out + X_OFF + xidx);
                    float s0 = v0 + dr.x, s1 = v1 + dr.y;
                    unsigned lp, hp = pack_hilo(s0, s1, lp);
                    *(unsigned*)(g_h_hi + ci) = hp;
                    *(unsigned*)(g_h_lo + ci) = lp;
                } else {
                    unsigned chp = *(const unsigned*)(g_h_hi + ci);
                    unsigned clp = *(const unsigned*)(g_h_lo + ci);
                    __nv_bfloat162 ch = *(__nv_bfloat162*)&chp;
                    __nv_bfloat162 cl = *(__nv_bfloat162*)&clp;
                    float xv0 = v0 + bf2f(__low2bfloat16(ch)) + bf2f(__low2bfloat16(cl));
                    float xv1 = v1 + bf2f(__high2bfloat16(ch)) + bf2f(__high2bfloat16(cl));
                    *(float2*)(out + X_OFF + xidx) = make_float2(xv0, xv1);
                    float2 mn = *(const float2*)(XMIN + xidx);
                    float2 mx = *(const float2*)(XMAX + xidx);
                    *(float2*)(out + SXMIN_OFF + xidx) =
                        make_float2(fmaxf(mn.x - xv0, 0.f), fmaxf(mn.y - xv1, 0.f));
                    *(float2*)(out + SXMAX_OFF + xidx) =
                        make_float2(fmaxf(xv0 - mx.x, 0.f), fmaxf(xv1 - mx.y, 0.f));
                    if (c == 254) out[Y_OFF + (size_t)t * 256 + batch] = xv1;
                }
            }
        }
    }
}

// ---------------- carry scan: s_{b+1} = s_b @ A^8 + c_{b,7}, 63 steps ----------------
struct ScanSmem {
    float A[256][128];
    ulonglong2 xs2[2][256];
    unsigned long long part[4][64][2][2];
};

__global__ void __launch_bounds__(256, 1) __cluster_dims__(2, 1, 1)
carry_scan_kernel(const float* __restrict__ x0) {
    extern __shared__ char smem_raw[];
    ScanSmem* S = reinterpret_cast<ScanSmem*>(smem_raw);
    int tid = threadIdx.x;
    unsigned rank = ctarank();
    int b0 = (int)(blockIdx.x >> 1) * 4;

    const float* A8 = g_P + 7 * 65536;
#pragma unroll
    for (int it = 0; it < 32; it++) {
        int idx4 = tid + it * 256;
        int j = idx4 >> 5;
        int c4 = idx4 & 31;
        float4 v = *(const float4*)(A8 + (size_t)j * 256 + rank * 128 + c4 * 4);
        *(float4*)(&S->A[j][c4 * 4]) = v;
    }
    {
        int j = tid;
        float a[4];
#pragma unroll
        for (int r = 0; r < 4; r++) {
            a[r] = x0[(b0 + r) * 256 + j];
            __nv_bfloat16 h, l;
            split1(a[r], h, l);
            size_t si = (size_t)(b0 + r) * 256 + j;  // s_0 rows = batch
            g_u_hi[si] = h;
            g_u_lo[si] = l;
        }
        S->xs2[0][j] = make_ulonglong2(pk2(a[0], a[1]), pk2(a[2], a[3]));
    }
    __syncthreads();

    const int jj = tid >> 6;
    const int cp = tid & 63;
    const int il = tid & 127;
    const int h  = tid >> 7;
    const int gcol = (int)rank * 128 + il;

    const __nv_bfloat16* c7h = g_h_hi + (size_t)7 * CSTRIDE;
    const __nv_bfloat16* c7l = g_h_lo + (size_t)7 * CSTRIDE;

    float pf_d0, pf_d1;
    {
        size_t ci = ((size_t)(b0 + 2 * h)) * 256 + gcol;  // b=0
        pf_d0 = bf2f(c7h[ci]) + bf2f(c7l[ci]);
        pf_d1 = bf2f(c7h[ci + 256]) + bf2f(c7l[ci + 256]);
    }

    for (int b = 0; b < 63; b++) {
        int p = b & 1;
        unsigned long long a00 = 0, a01 = 0, a10 = 0, a11 = 0;
        const ulonglong2* xb = S->xs2[p];
        const float2* Arow = (const float2*)&S->A[jj * 64][0] + cp;
#pragma unroll 8
        for (int it = 0; it < 64; it++) {
            int jq = jj * 64 + it;
            float2 a = Arow[(size_t)it * 64];
            ulonglong2 xv = xb[jq];
            unsigned long long b0p = bcast2(a.x), b1p = bcast2(a.y);
            fma2(a00, b0p, xv.x);
            fma2(a01, b0p, xv.y);
            fma2(a10, b1p, xv.x);
            fma2(a11, b1p, xv.y);
        }
        S->part[jj][cp][0][0] = a00;
        S->part[jj][cp][0][1] = a01;
        S->part[jj][cp][1][0] = a10;
        S->part[jj][cp][1][1] = a11;
        __syncthreads();

        int cp2 = il >> 1, cip = il & 1;
        unsigned long long s = S->part[0][cp2][cip][h];
        add2(s, S->part[1][cp2][cip][h]);
        add2(s, S->part[2][cp2][cip][h]);
        add2(s, S->part[3][cp2][cip][h]);
        float2 sv = unpk(s);
        float v0 = sv.x + pf_d0;
        float v1 = sv.y + pf_d1;

        // write s_{b+1} hi/lo
        {
            size_t row0 = (size_t)(b + 1) * 256 + b0 + 2 * h;
            __nv_bfloat16 hh, ll;
            split1(v0, hh, ll);
            g_u_hi[row0 * 256 + gcol] = hh;
            g_u_lo[row0 * 256 + gcol] = ll;
            split1(v1, hh, ll);
            g_u_hi[(row0 + 1) * 256 + gcol] = hh;
            g_u_lo[(row0 + 1) * 256 + gcol] = ll;
        }

        unsigned long long xn = pk2(v0, v1);
        unsigned long long* dst =
            (h == 0) ? &S->xs2[p ^ 1][gcol].x : &S->xs2[p ^ 1][gcol].y;
        *dst = xn;
        unsigned laddr = smem_u32(dst);
        unsigned raddr;
        asm("mapa.shared::cluster.u32 %0, %1, %2;" : "=r"(raddr) : "r"(laddr), "r"(rank ^ 1u));
        asm volatile("st.shared::cluster.u64 [%0], %1;" :: "r"(raddr), "l"(xn) : "memory");

        int bn = (b < 62) ? b + 1 : 62;
        size_t cin = ((size_t)bn * 256 + b0 + 2 * h) * 256 + gcol;
        pf_d0 = bf2f(c7h[cin]) + bf2f(c7l[cin]);
        pf_d1 = bf2f(c7h[cin + 256]) + bf2f(c7l[cin + 256]);

        asm volatile("barrier.cluster.arrive.aligned;" ::: "memory");
        asm volatile("barrier.cluster.wait.aligned;" ::: "memory");
    }
}

// ---------------- launch ----------------
extern "C" void kernel_launch(void* const* d_in, const int* in_sizes, int n_in,
                              void* d_out, int out_size) {
    const float* x      = (const float*)d_in[0];
    const float* M_flow = (const float*)d_in[1];
    const float* DT     = (const float*)d_in[2];
    const float* D      = (const float*)d_in[3];
    const float* XMIN   = (const float*)d_in[4];
    const float* XMAX   = (const float*)d_in[5];
    const float* UMIN   = (const float*)d_in[6];
    const float* UMAX   = (const float*)d_in[7];
    const float* A_w    = (const float*)d_in[8];
    const float* A_sc   = (const float*)d_in[9];
    const float* B_W    = (const float*)d_in[10];
    const float* E_W    = (const float*)d_in[11];
    const float* hf1_W  = (const float*)d_in[12];
    const float* hf2_W  = (const float*)d_in[13];
    float* out = (float*)d_out;

    build_aeff_kernel<<<256, 256>>>(A_w, A_sc);
    pow_kernel<<<dim3(256, 1, 1), 256>>>(0, 0, 1);
    pow_kernel<<<dim3(256, 1, 2), 256>>>(1, 0, 2);
    pow_kernel<<<dim3(256, 1, 4), 256>>>(3, 0, 4);
    transp_kernel<<<dim3(8, 8, 8), dim3(32, 8)>>>();

    const int gsmem = 4 * 128 * SROW;  // 73728
    cudaFuncSetAttribute(gemm_mma_kernel<0>, cudaFuncAttributeMaxDynamicSharedMemorySize, gsmem);
    cudaFuncSetAttribute(gemm_mma_kernel<1>, cudaFuncAttributeMaxDynamicSharedMemorySize, gsmem);
    cudaFuncSetAttribute(gemm_mma_kernel<2>, cudaFuncAttributeMaxDynamicSharedMemorySize, gsmem);
    cudaFuncSetAttribute(blockscan_gemm<0>, cudaFuncAttributeMaxDynamicSharedMemorySize, gsmem);
    cudaFuncSetAttribute(blockscan_gemm<1>, cudaFuncAttributeMaxDynamicSharedMemorySize, gsmem);

    gemm_mma_kernel<0><<<dim3(4, 1024), 256, gsmem>>>(M_flow, DT, hf1_W, nullptr, nullptr, nullptr, out);
    gemm_mma_kernel<1><<<dim3(2, 1024), 256, gsmem>>>(nullptr, nullptr, hf2_W, nullptr, UMIN, UMAX, out);
    gemm_mma_kernel<2><<<dim3(2, 1024), 256, gsmem>>>(nullptr, D, B_W, E_W, nullptr, nullptr, out);

    // block-scan replacement
    c0init_kernel<<<16384, 256>>>(out);
    for (int j = 1; j <= 7; j++)
        blockscan_gemm<0><<<dim3(2, 128), 256, gsmem>>>(j, nullptr, nullptr, out);

    cudaFuncSetAttribute(carry_scan_kernel, cudaFuncAttributeMaxDynamicSharedMemorySize,
                         (int)sizeof(ScanSmem));
    carry_scan_kernel<<<128, 256, sizeof(ScanSmem)>>>(x);

    blockscan_gemm<1><<<dim3(2, 128, 8), 256, gsmem>>>(0, XMIN, XMAX, out);
}